// round 3
// baseline (speedup 1.0000x reference)
#include <cuda_runtime.h>
#include <cstdint>

// ---------------------------------------------------------------------------
// FeatureAttentionPerFeature
//   scores[b,f] = feat_f[b] . (Wk_f^T q) / sqrt(128)       (K GEMM eliminated)
//   w = softmax_f(scores)
//   combined[b] = Wv_all @ (w-scaled concatenated feats)   (single fp32 GEMM)
// Output layout: [ combined (B*128) | attn_weights (B*8) ]
// Inputs bound BY SIZE (robust to metadata ordering).
// ---------------------------------------------------------------------------

#define NF     8
#define HID    128
#define KTOT   1664
#define BATCHN 32768
#define BR     128      // rows per block
#define KC     32       // k-chunk (never crosses a feature boundary)
#define NCHUNK (KTOT / KC)   // 52

// compile-time tables (device-visible, fold to immediates in unrolled loops)
__device__ constexpr int DIMS_C[NF]   = {32, 64, 96, 128, 192, 256, 384, 512};
__device__ constexpr int OFFS_C[NF+1] = {0, 32, 96, 192, 320, 512, 768, 1152, 1664};

__constant__ int gDIMS[NF]   = {32, 64, 96, 128, 192, 256, 384, 512};
__constant__ int gOFFS[NF+1] = {0, 32, 96, 192, 320, 512, 768, 1152, 1664};
// chunk index (k0 = 32*ch) -> feature id
__constant__ unsigned char gCHF[NCHUNK] = {
    0,
    1,1,
    2,2,2,
    3,3,3,3,
    4,4,4,4,4,4,
    5,5,5,5,5,5,5,5,
    6,6,6,6,6,6,6,6,6,6,6,6,
    7,7,7,7,7,7,7,7,7,7,7,7,7,7,7,7
};

// device scratch (no allocations allowed)
__device__ float g_c[KTOT];          // Wk_f^T q / sqrt(128), concatenated
__device__ float g_Wp[KTOT * HID];   // packed Wv, k-major: g_Wp[k*128 + h]

struct Ptrs {
    const float* feat[NF];
    const float* Wk[NF];
    const float* Wv[NF];
    const float* q;
};

// ---------------------------------------------------------------------------
// f32x2 packed-math helpers (Blackwell FFMA2 path)
// ---------------------------------------------------------------------------
__device__ __forceinline__ unsigned long long pack2(float x, float y) {
    unsigned long long r;
    asm("mov.b64 %0, {%1, %2};" : "=l"(r) : "f"(x), "f"(y));
    return r;
}
__device__ __forceinline__ void ffma2(unsigned long long& d,
                                      unsigned long long a,
                                      unsigned long long b) {
    asm("fma.rn.f32x2 %0, %1, %2, %0;" : "+l"(d) : "l"(a), "l"(b));
}
__device__ __forceinline__ float2 unpack2(unsigned long long v) {
    float2 r;
    asm("mov.b64 {%0, %1}, %2;" : "=f"(r.x), "=f"(r.y) : "l"(v));
    return r;
}

// ---------------------------------------------------------------------------
// prep: c = Wk^T q / sqrt(H); pack Wv into k-major g_Wp
// grid: 832 x 256 threads = 212992 = KTOT*HID
// ---------------------------------------------------------------------------
__global__ void prep_kernel(Ptrs p) {
    int tid = blockIdx.x * blockDim.x + threadIdx.x;

    if (tid < KTOT) {
        int f = 0;
        while (tid >= gOFFS[f + 1]) f++;
        int j = tid - gOFFS[f];
        int d = gDIMS[f];
        const float* W = p.Wk[f];
        float s = 0.f;
        #pragma unroll 4
        for (int h = 0; h < HID; h++) s += W[h * d + j] * p.q[h];
        g_c[tid] = s * 0.08838834764831845f;  // 1/sqrt(128)
    }

    // pack Wv: s = k*128 + h  (coalesced writes)
    int s = tid;
    if (s < KTOT * HID) {
        int k = s >> 7;
        int h = s & 127;
        int f = 0;
        while (k >= gOFFS[f + 1]) f++;
        int j = k - gOFFS[f];
        g_Wp[s] = p.Wv[f][h * gDIMS[f] + j];
    }
}

// ---------------------------------------------------------------------------
// main: per-128-row block -> scores/softmax, then 128x128 GEMM tile over K=1664
// ---------------------------------------------------------------------------
__global__ __launch_bounds__(256, 2)
void main_kernel(Ptrs p, float* __restrict__ out) {
    __shared__ float As[KC][132];      // Xw tile, k-major, padded rows
    __shared__ float Bs[KC][HID];      // Wv tile, k-major
    __shared__ float ws[BR][NF];       // softmax weights
    __shared__ float cs[KTOT];         // score vector

    const int t    = threadIdx.x;
    const int row0 = blockIdx.x * BR;

    // stage c into shared
    for (int i = t; i < KTOT; i += 256) cs[i] = g_c[i];
    __syncthreads();

    // ---- phase 1: scores + softmax (threads 0..127, one row each) ----
    if (t < BR) {
        const int row = row0 + t;
        float sc[NF];
        #pragma unroll
        for (int f = 0; f < NF; f++) {
            const int d = DIMS_C[f];
            const float* fp = p.feat[f] + (size_t)row * d;
            const float* cp = cs + OFFS_C[f];
            float s0 = 0.f, s1 = 0.f, s2 = 0.f, s3 = 0.f;
            #pragma unroll 4
            for (int j = 0; j < d; j += 4) {
                s0 += fp[j + 0] * cp[j + 0];
                s1 += fp[j + 1] * cp[j + 1];
                s2 += fp[j + 2] * cp[j + 2];
                s3 += fp[j + 3] * cp[j + 3];
            }
            sc[f] = (s0 + s1) + (s2 + s3);
        }
        float m = sc[0];
        #pragma unroll
        for (int f = 1; f < NF; f++) m = fmaxf(m, sc[f]);
        float sum = 0.f;
        #pragma unroll
        for (int f = 0; f < NF; f++) { sc[f] = expf(sc[f] - m); sum += sc[f]; }
        const float inv = 1.f / sum;
        #pragma unroll
        for (int f = 0; f < NF; f++) {
            float w = sc[f] * inv;
            ws[t][f] = w;
            out[(size_t)BATCHN * HID + (size_t)row * NF + f] = w;
        }
    }
    __syncthreads();

    // ---- phase 2: GEMM  combined(128x128) += As(128xK) * Bs(Kx128) ----
    const int i0 = (t >> 4) * 8;   // row sub-tile
    const int j0 = (t & 15) * 8;   // col sub-tile

    unsigned long long acc[8][4];  // 8 rows x 8 cols as f32x2 pairs
    #pragma unroll
    for (int r = 0; r < 8; r++)
        #pragma unroll
        for (int c = 0; c < 4; c++) acc[r][c] = 0ull;

    for (int ch = 0; ch < NCHUNK; ch++) {
        const int k0 = ch * KC;
        const int f  = gCHF[ch];
        const int d  = gDIMS[f];
        const int lc = k0 - gOFFS[f];
        const float* fbase = p.feat[f];

        // load Bs (coalesced, already k-major in g_Wp)
        {
            const float4* src = (const float4*)(g_Wp + (size_t)k0 * HID);
            float4* dst = (float4*)Bs;
            #pragma unroll
            for (int i = 0; i < 4; i++) dst[i * 256 + t] = src[i * 256 + t];
        }
        // load As: coalesced float4 global reads, transposed + scaled stores
        #pragma unroll
        for (int i = 0; i < 4; i++) {
            int lin = i * 256 + t;         // 0..1023
            int row = lin >> 3;            // 0..127
            int q4  = lin & 7;             // 0..7
            float w = ws[row][f];
            float4 v = *(const float4*)(fbase + (size_t)(row0 + row) * d + lc + q4 * 4);
            int kk = q4 * 4;
            As[kk + 0][row] = v.x * w;
            As[kk + 1][row] = v.y * w;
            As[kk + 2][row] = v.z * w;
            As[kk + 3][row] = v.w * w;
        }
        __syncthreads();

        #pragma unroll 8
        for (int kk = 0; kk < KC; kk++) {
            float4 a0 = *(const float4*)&As[kk][i0];
            float4 a1 = *(const float4*)&As[kk][i0 + 4];
            float4 b0 = *(const float4*)&Bs[kk][j0];
            float4 b1 = *(const float4*)&Bs[kk][j0 + 4];
            unsigned long long bp0 = pack2(b0.x, b0.y);
            unsigned long long bp1 = pack2(b0.z, b0.w);
            unsigned long long bp2 = pack2(b1.x, b1.y);
            unsigned long long bp3 = pack2(b1.z, b1.w);
            float av[8] = {a0.x, a0.y, a0.z, a0.w, a1.x, a1.y, a1.z, a1.w};
            #pragma unroll
            for (int r = 0; r < 8; r++) {
                unsigned long long ad = pack2(av[r], av[r]);
                ffma2(acc[r][0], ad, bp0);
                ffma2(acc[r][1], ad, bp1);
                ffma2(acc[r][2], ad, bp2);
                ffma2(acc[r][3], ad, bp3);
            }
        }
        __syncthreads();
    }

    // ---- epilogue: write combined ----
    #pragma unroll
    for (int r = 0; r < 8; r++) {
        size_t o = (size_t)(row0 + i0 + r) * HID + j0;
        float2 p0 = unpack2(acc[r][0]);
        float2 p1 = unpack2(acc[r][1]);
        float2 p2 = unpack2(acc[r][2]);
        float2 p3 = unpack2(acc[r][3]);
        *(float4*)(out + o)     = make_float4(p0.x, p0.y, p1.x, p1.y);
        *(float4*)(out + o + 4) = make_float4(p2.x, p2.y, p3.x, p3.y);
    }
}

// ---------------------------------------------------------------------------
// Bind inputs by element count — robust to metadata ordering.
//   query       : 128 elements (unique)
//   feat_f      : 32768 * d_f  (all unique, >= 1M)
//   Wk_f / Wv_f : 128 * d_f    (each size appears exactly twice; Wk precedes
//                               Wv in any plausible metadata ordering)
// ---------------------------------------------------------------------------
extern "C" void kernel_launch(void* const* d_in, const int* in_sizes, int n_in,
                              void* d_out, int out_size) {
    static const int dims[NF] = {32, 64, 96, 128, 192, 256, 384, 512};
    Ptrs p;
    int wseen[NF] = {0};

    for (int i = 0; i < n_in; i++) {
        const float* ptr = (const float*)d_in[i];
        int s = in_sizes[i];
        if (s == HID) { p.q = ptr; continue; }
        bool matched = false;
        for (int f = 0; f < NF; f++) {
            if (s == BATCHN * dims[f]) { p.feat[f] = ptr; matched = true; break; }
        }
        if (matched) continue;
        for (int f = 0; f < NF; f++) {
            if (s == HID * dims[f]) {
                if (!wseen[f]) { p.Wk[f] = ptr; wseen[f] = 1; }
                else           { p.Wv[f] = ptr; }
                break;
            }
        }
    }

    prep_kernel<<<(KTOT * HID) / 256, 256>>>(p);
    main_kernel<<<BATCHN / BR, 256>>>(p, (float*)d_out);
}

// round 6
// speedup vs baseline: 2.9229x; 2.9229x over previous
#include <cuda_runtime.h>
#include <cuda_bf16.h>
#include <cstdint>

// ---------------------------------------------------------------------------
// FeatureAttentionPerFeature — mma.sync bf16 3-term split (baseline PTX, no 'a')
//   scores[b,f] = feat_f[b] . (Wk_f^T q)/sqrt(128)
//   w = softmax_f(scores)
//   combined = (w-scaled concat feats) @ Wv_all^T
// Output: [ combined (B*128) | attn_weights (B*8) ]
// ---------------------------------------------------------------------------

#define NF     8
#define HID    128
#define KTOT   1664
#define BATCHN 32768
#define MBLK   128
#define KCH    64
#define NCH    (KTOT/KCH)    // 26
#define NTHR   256
#define RSTRIDE 144          // smem row stride in BYTES (72 bf16): conflict-free

__device__ constexpr int DIMS_C[NF]   = {32, 64, 96, 128, 192, 256, 384, 512};
__device__ constexpr int OFFS_C[NF+1] = {0, 32, 96, 192, 320, 512, 768, 1152, 1664};
__constant__ int gDIMS[NF]   = {32, 64, 96, 128, 192, 256, 384, 512};
__constant__ int gOFFS[NF+1] = {0, 32, 96, 192, 320, 512, 768, 1152, 1664};

// device scratch
__device__ float g_c[KTOT];
__device__ __nv_bfloat16 g_Bh[HID * KTOT];   // Wv hi, [n][k] k-major
__device__ __nv_bfloat16 g_Bl[HID * KTOT];   // Wv lo residual

struct Ptrs {
    const float* feat[NF];
    const float* Wk[NF];
    const float* Wv[NF];
    const float* q;
};

// ---------------- helpers ----------------
__device__ __forceinline__ uint32_t smem_u32(const void* p) {
    uint32_t a;
    asm("{ .reg .u64 t; cvta.to.shared.u64 t, %1; cvt.u32.u64 %0, t; }" : "=r"(a) : "l"(p));
    return a;
}
__device__ __forceinline__ void ldsm_x4(uint32_t* r, uint32_t a) {
    asm volatile("ldmatrix.sync.aligned.m8n8.x4.shared.b16 {%0,%1,%2,%3}, [%4];"
                 : "=r"(r[0]), "=r"(r[1]), "=r"(r[2]), "=r"(r[3]) : "r"(a));
}
__device__ __forceinline__ void mma_bf16(float* c, const uint32_t* a, const uint32_t* b) {
    asm volatile(
        "mma.sync.aligned.m16n8k16.row.col.f32.bf16.bf16.f32 "
        "{%0,%1,%2,%3}, {%4,%5,%6,%7}, {%8,%9}, {%0,%1,%2,%3};"
        : "+f"(c[0]), "+f"(c[1]), "+f"(c[2]), "+f"(c[3])
        : "r"(a[0]), "r"(a[1]), "r"(a[2]), "r"(a[3]), "r"(b[0]), "r"(b[1]));
}
__device__ __forceinline__ int ffind(int k) {
    int f = 7;
    if (k < 1152) f = 6;
    if (k < 768)  f = 5;
    if (k < 512)  f = 4;
    if (k < 320)  f = 3;
    if (k < 192)  f = 2;
    if (k < 96)   f = 1;
    if (k < 32)   f = 0;
    return f;
}

// ---------------- SMEM layout (dynamic, bytes) ----------------
#define OFF_CS  0                        // 1664*4 = 6656
#define OFF_WS  6656                     // 128*8*4 = 4096
#define OFF_AH  10752                    // 128*144 = 18432
#define OFF_AL  (OFF_AH + 18432)
#define OFF_BH  (OFF_AL + 18432)
#define OFF_BL  (OFF_BH + 18432)
#define SMEM_TOT (OFF_BL + 18432)        // 84480

// ---------------------------------------------------------------------------
// prep: c vector (warp per k) + bf16 hi/lo pack of Wv into [n][k]
// ---------------------------------------------------------------------------
__global__ void prep_kernel(Ptrs p) {
    int tid = blockIdx.x * blockDim.x + threadIdx.x;

    if (tid < KTOT * 32) {
        int k = tid >> 5, ln = tid & 31;
        int f = ffind(k);
        int j = k - gOFFS[f];
        int d = gDIMS[f];
        const float* W = p.Wk[f];
        float s = 0.f;
        #pragma unroll
        for (int h = ln; h < HID; h += 32) s += W[h * d + j] * p.q[h];
        #pragma unroll
        for (int o = 16; o; o >>= 1) s += __shfl_xor_sync(0xffffffffu, s, o);
        if (ln == 0) g_c[k] = s * 0.08838834764831845f;
    }

    if (tid < HID * KTOT) {
        int n = tid / KTOT;
        int k = tid % KTOT;
        int f = ffind(k);
        int j = k - gOFFS[f];
        float val = p.Wv[f][n * gDIMS[f] + j];
        __nv_bfloat16 hi = __float2bfloat16_rn(val);
        __nv_bfloat16 lo = __float2bfloat16_rn(val - __bfloat162float(hi));
        g_Bh[tid] = hi;
        g_Bl[tid] = lo;
    }
}

// ---------------------------------------------------------------------------
// main kernel: grid 256 x 256 threads, 2 CTAs/SM
// ---------------------------------------------------------------------------
__global__ void __launch_bounds__(NTHR, 2)
main_kernel(Ptrs p, float* __restrict__ out) {
    extern __shared__ char smem[];
    const uint32_t sb = smem_u32(smem);
    const int t    = threadIdx.x;
    const int lane = t & 31;
    const int wid  = t >> 5;
    const int wm   = wid >> 2;          // 0..1  (64 rows each)
    const int wn   = wid & 3;           // 0..3  (32 cols each)
    const int row0 = blockIdx.x * MBLK;

    float* cs   = (float*)(smem + OFF_CS);
    float* ws_s = (float*)(smem + OFF_WS);

    for (int i = t; i < KTOT; i += NTHR) cs[i] = g_c[i];
    __syncthreads();

    // ---- phase 1: scores + softmax (threads 0..127, one row each) ----
    if (t < MBLK) {
        const int row = row0 + t;
        float sc[NF];
        #pragma unroll
        for (int f = 0; f < NF; f++) {
            const int d = DIMS_C[f];
            const float4* fp = (const float4*)(p.feat[f] + (size_t)row * d);
            const float4* cp = (const float4*)(cs + OFFS_C[f]);
            float s0 = 0.f, s1 = 0.f, s2 = 0.f, s3 = 0.f;
            #pragma unroll 4
            for (int j = 0; j < d / 4; j++) {
                float4 a = fp[j], b = cp[j];
                s0 += a.x * b.x; s1 += a.y * b.y;
                s2 += a.z * b.z; s3 += a.w * b.w;
            }
            sc[f] = (s0 + s1) + (s2 + s3);
        }
        float m = sc[0];
        #pragma unroll
        for (int f = 1; f < NF; f++) m = fmaxf(m, sc[f]);
        float sum = 0.f;
        #pragma unroll
        for (int f = 0; f < NF; f++) { sc[f] = expf(sc[f] - m); sum += sc[f]; }
        const float inv = 1.f / sum;
        #pragma unroll
        for (int f = 0; f < NF; f++) {
            float w = sc[f] * inv;
            ws_s[t * NF + f] = w;
            out[(size_t)BATCHN * HID + (size_t)row * NF + f] = w;
        }
    }

    // ---- mainloop ----
    float acc[4][4][4];
    #pragma unroll
    for (int mf = 0; mf < 4; mf++)
        #pragma unroll
        for (int nf = 0; nf < 4; nf++)
            #pragma unroll
            for (int r = 0; r < 4; r++) acc[mf][nf][r] = 0.f;

    // per-lane ldmatrix base offsets (bytes)
    const uint32_t aoff = (uint32_t)((wm * 64 + (lane & 15)) * RSTRIDE + ((lane >> 4) * 8) * 2);
    const uint32_t boff = (uint32_t)((wn * 32 + ((lane >> 4) * 8) + (lane & 7)) * RSTRIDE +
                                     (((lane >> 3) & 1) * 8) * 2);
    const uint32_t sAh = sb + OFF_AH, sAl = sb + OFF_AL;
    const uint32_t sBh = sb + OFF_BH, sBl = sb + OFF_BL;

    for (int ch = 0; ch < NCH; ch++) {
        const int k0 = ch * KCH;
        __syncthreads();   // previous chunk's ldmatrix done

        // --- A convert: 128 rows x 64 k, hi/lo bf16, weight-scaled ---
        #pragma unroll
        for (int it = 0; it < 4; it++) {
            int g   = it * 256 + t;        // 0..1023
            int row = g >> 3;
            int kq  = g & 7;
            int kg  = k0 + kq * 8;
            int f   = ffind(kg);
            int j   = kg - gOFFS[f];
            const float* src = p.feat[f] + (size_t)(row0 + row) * gDIMS[f] + j;
            float4 v0 = *(const float4*)src;
            float4 v1 = *(const float4*)(src + 4);
            float w = ws_s[row * NF + f];
            float x[8] = {v0.x * w, v0.y * w, v0.z * w, v0.w * w,
                          v1.x * w, v1.y * w, v1.z * w, v1.w * w};
            uint32_t h[4], l[4];
            #pragma unroll
            for (int q = 0; q < 4; q++) {
                float a0 = x[2 * q], a1 = x[2 * q + 1];
                __nv_bfloat16 b0 = __float2bfloat16_rn(a0);
                __nv_bfloat16 b1 = __float2bfloat16_rn(a1);
                __nv_bfloat16 c0 = __float2bfloat16_rn(a0 - __bfloat162float(b0));
                __nv_bfloat16 c1 = __float2bfloat16_rn(a1 - __bfloat162float(b1));
                h[q] = (uint32_t)__bfloat16_as_ushort(b0) | ((uint32_t)__bfloat16_as_ushort(b1) << 16);
                l[q] = (uint32_t)__bfloat16_as_ushort(c0) | ((uint32_t)__bfloat16_as_ushort(c1) << 16);
            }
            uint32_t off = (uint32_t)(row * RSTRIDE + kq * 16);
            *(uint4*)(smem + OFF_AH + off) = make_uint4(h[0], h[1], h[2], h[3]);
            *(uint4*)(smem + OFF_AL + off) = make_uint4(l[0], l[1], l[2], l[3]);
        }
        // --- B tiles: copy from packed global (L2-resident) ---
        #pragma unroll
        for (int it = 0; it < 4; it++) {
            int g  = it * 256 + t;         // 0..1023
            int n  = g >> 3;
            int kq = g & 7;
            size_t goff = (size_t)n * KTOT + k0 + kq * 8;
            uint32_t off = (uint32_t)(n * RSTRIDE + kq * 16);
            *(uint4*)(smem + OFF_BH + off) = *(const uint4*)&g_Bh[goff];
            *(uint4*)(smem + OFF_BL + off) = *(const uint4*)&g_Bl[goff];
        }
        __syncthreads();

        // --- tensor-core phase: 4 k16 steps ---
        #pragma unroll
        for (int ks = 0; ks < 4; ks++) {
            const uint32_t koff = ks * 32;   // 16 bf16 = 32 bytes
            uint32_t a[4][4];
            #pragma unroll
            for (int mf = 0; mf < 4; mf++)
                ldsm_x4(a[mf], sAh + aoff + mf * (16 * RSTRIDE) + koff);

            uint32_t bh[4][2], bl[4][2];
            #pragma unroll
            for (int bq = 0; bq < 2; bq++) {
                uint32_t r[4];
                // B stored [n][k] k-contiguous -> NON-trans ldmatrix yields the
                // m16n8k16 row.col B fragment (lane: n = l>>2, two consecutive k)
                ldsm_x4(r, sBh + boff + bq * (16 * RSTRIDE) + koff);
                bh[bq * 2][0] = r[0]; bh[bq * 2][1] = r[1];
                bh[bq * 2 + 1][0] = r[2]; bh[bq * 2 + 1][1] = r[3];
                ldsm_x4(r, sBl + boff + bq * (16 * RSTRIDE) + koff);
                bl[bq * 2][0] = r[0]; bl[bq * 2][1] = r[1];
                bl[bq * 2 + 1][0] = r[2]; bl[bq * 2 + 1][1] = r[3];
            }
            #pragma unroll
            for (int mf = 0; mf < 4; mf++)
                #pragma unroll
                for (int nf = 0; nf < 4; nf++) mma_bf16(acc[mf][nf], a[mf], bh[nf]);
            #pragma unroll
            for (int mf = 0; mf < 4; mf++)
                #pragma unroll
                for (int nf = 0; nf < 4; nf++) mma_bf16(acc[mf][nf], a[mf], bl[nf]);
            // reload A lo over a[]
            #pragma unroll
            for (int mf = 0; mf < 4; mf++)
                ldsm_x4(a[mf], sAl + aoff + mf * (16 * RSTRIDE) + koff);
            #pragma unroll
            for (int mf = 0; mf < 4; mf++)
                #pragma unroll
                for (int nf = 0; nf < 4; nf++) mma_bf16(acc[mf][nf], a[mf], bh[nf]);
        }
    }

    // ---- epilogue: write combined ----
    #pragma unroll
    for (int mf = 0; mf < 4; mf++) {
        #pragma unroll
        for (int nf = 0; nf < 4; nf++) {
            int r0 = row0 + wm * 64 + mf * 16 + (lane >> 2);
            int c  = wn * 32 + nf * 8 + (lane & 3) * 2;
            *(float2*)(out + (size_t)r0 * HID + c) =
                make_float2(acc[mf][nf][0], acc[mf][nf][1]);
            *(float2*)(out + (size_t)(r0 + 8) * HID + c) =
                make_float2(acc[mf][nf][2], acc[mf][nf][3]);
        }
    }
}

// ---------------------------------------------------------------------------
extern "C" void kernel_launch(void* const* d_in, const int* in_sizes, int n_in,
                              void* d_out, int out_size) {
    static const int dims[NF] = {32, 64, 96, 128, 192, 256, 384, 512};
    Ptrs p;
    int wseen[NF] = {0};

    for (int i = 0; i < n_in; i++) {
        const float* ptr = (const float*)d_in[i];
        int s = in_sizes[i];
        if (s == HID) { p.q = ptr; continue; }
        bool matched = false;
        for (int f = 0; f < NF; f++)
            if (s == BATCHN * dims[f]) { p.feat[f] = ptr; matched = true; break; }
        if (matched) continue;
        for (int f = 0; f < NF; f++)
            if (s == HID * dims[f]) {
                if (!wseen[f]) { p.Wk[f] = ptr; wseen[f] = 1; }
                else           { p.Wv[f] = ptr; }
                break;
            }
    }

    cudaFuncSetAttribute(main_kernel, cudaFuncAttributeMaxDynamicSharedMemorySize, SMEM_TOT);

    prep_kernel<<<(HID * KTOT + 255) / 256, 256>>>(p);
    main_kernel<<<BATCHN / MBLK, NTHR, SMEM_TOT>>>(p, (float*)d_out);
}

// round 7
// speedup vs baseline: 3.2861x; 1.1243x over previous
#include <cuda_runtime.h>
#include <cuda_bf16.h>
#include <cstdint>

// ---------------------------------------------------------------------------
// FeatureAttentionPerFeature — mma.sync bf16 3-term split (baseline PTX, no 'a')
//   scores[b,f] = feat_f[b] . (Wk_f^T q)/sqrt(128)
//   w = softmax_f(scores)
//   combined = (w-scaled concat feats) @ Wv_all^T
// Output: [ combined (B*128) | attn_weights (B*8) ]
// R7: coalesced warp-per-row phase 1 (was 32-wavefront/instr scattered reads)
// ---------------------------------------------------------------------------

#define NF     8
#define HID    128
#define KTOT   1664
#define BATCHN 32768
#define MBLK   128
#define KCH    64
#define NCH    (KTOT/KCH)    // 26
#define NTHR   256
#define RSTRIDE 144          // smem row stride in BYTES (72 bf16): conflict-free

__device__ constexpr int DIMS_C[NF]   = {32, 64, 96, 128, 192, 256, 384, 512};
__device__ constexpr int OFFS_C[NF+1] = {0, 32, 96, 192, 320, 512, 768, 1152, 1664};
__constant__ int gDIMS[NF]   = {32, 64, 96, 128, 192, 256, 384, 512};
__constant__ int gOFFS[NF+1] = {0, 32, 96, 192, 320, 512, 768, 1152, 1664};

// device scratch
__device__ float g_c[KTOT];
__device__ __nv_bfloat16 g_Bh[HID * KTOT];   // Wv hi, [n][k] k-major
__device__ __nv_bfloat16 g_Bl[HID * KTOT];   // Wv lo residual

struct Ptrs {
    const float* feat[NF];
    const float* Wk[NF];
    const float* Wv[NF];
    const float* q;
};

// ---------------- helpers ----------------
__device__ __forceinline__ uint32_t smem_u32(const void* p) {
    uint32_t a;
    asm("{ .reg .u64 t; cvta.to.shared.u64 t, %1; cvt.u32.u64 %0, t; }" : "=r"(a) : "l"(p));
    return a;
}
__device__ __forceinline__ void ldsm_x4(uint32_t* r, uint32_t a) {
    asm volatile("ldmatrix.sync.aligned.m8n8.x4.shared.b16 {%0,%1,%2,%3}, [%4];"
                 : "=r"(r[0]), "=r"(r[1]), "=r"(r[2]), "=r"(r[3]) : "r"(a));
}
__device__ __forceinline__ void mma_bf16(float* c, const uint32_t* a, const uint32_t* b) {
    asm volatile(
        "mma.sync.aligned.m16n8k16.row.col.f32.bf16.bf16.f32 "
        "{%0,%1,%2,%3}, {%4,%5,%6,%7}, {%8,%9}, {%0,%1,%2,%3};"
        : "+f"(c[0]), "+f"(c[1]), "+f"(c[2]), "+f"(c[3])
        : "r"(a[0]), "r"(a[1]), "r"(a[2]), "r"(a[3]), "r"(b[0]), "r"(b[1]));
}
__device__ __forceinline__ int ffind(int k) {
    int f = 7;
    if (k < 1152) f = 6;
    if (k < 768)  f = 5;
    if (k < 512)  f = 4;
    if (k < 320)  f = 3;
    if (k < 192)  f = 2;
    if (k < 96)   f = 1;
    if (k < 32)   f = 0;
    return f;
}

// ---------------- SMEM layout (dynamic, bytes) ----------------
#define OFF_CS  0                        // 1664*4 = 6656
#define OFF_WS  6656                     // 128*8*4 = 4096
#define OFF_AH  10752                    // 128*144 = 18432
#define OFF_AL  (OFF_AH + 18432)
#define OFF_BH  (OFF_AL + 18432)
#define OFF_BL  (OFF_BH + 18432)
#define SMEM_TOT (OFF_BL + 18432)        // 84480

// ---------------------------------------------------------------------------
// prep: c vector (warp per k) + bf16 hi/lo pack of Wv into [n][k]
// ---------------------------------------------------------------------------
__global__ void prep_kernel(Ptrs p) {
    int tid = blockIdx.x * blockDim.x + threadIdx.x;

    if (tid < KTOT * 32) {
        int k = tid >> 5, ln = tid & 31;
        int f = ffind(k);
        int j = k - gOFFS[f];
        int d = gDIMS[f];
        const float* W = p.Wk[f];
        float s = 0.f;
        #pragma unroll
        for (int h = ln; h < HID; h += 32) s += W[h * d + j] * p.q[h];
        #pragma unroll
        for (int o = 16; o; o >>= 1) s += __shfl_xor_sync(0xffffffffu, s, o);
        if (ln == 0) g_c[k] = s * 0.08838834764831845f;
    }

    if (tid < HID * KTOT) {
        int n = tid / KTOT;
        int k = tid % KTOT;
        int f = ffind(k);
        int j = k - gOFFS[f];
        float val = p.Wv[f][n * gDIMS[f] + j];
        __nv_bfloat16 hi = __float2bfloat16_rn(val);
        __nv_bfloat16 lo = __float2bfloat16_rn(val - __bfloat162float(hi));
        g_Bh[tid] = hi;
        g_Bl[tid] = lo;
    }
}

// ---------------------------------------------------------------------------
// main kernel: grid 256 x 256 threads, 2 CTAs/SM
// ---------------------------------------------------------------------------
__global__ void __launch_bounds__(NTHR, 2)
main_kernel(Ptrs p, float* __restrict__ out) {
    extern __shared__ char smem[];
    const uint32_t sb = smem_u32(smem);
    const int t    = threadIdx.x;
    const int lane = t & 31;
    const int wid  = t >> 5;
    const int wm   = wid >> 2;          // 0..1  (64 rows each)
    const int wn   = wid & 3;           // 0..3  (32 cols each)
    const int row0 = blockIdx.x * MBLK;

    float* cs   = (float*)(smem + OFF_CS);
    float* ws_s = (float*)(smem + OFF_WS);

    for (int i = t; i < KTOT; i += NTHR) cs[i] = g_c[i];
    __syncthreads();

    // ---- phase 1: warp-per-row coalesced scores + softmax ----
    // Each warp handles 16 rows; all 32 lanes read consecutive float4s of ONE
    // row (fully coalesced, 4 wavefronts/instr instead of 32), shfl-reduce.
    {
        #pragma unroll 1
        for (int rr = 0; rr < 16; rr++) {
            const int lrow = wid * 16 + rr;
            const int row  = row0 + lrow;
            float sc[NF];
            #pragma unroll
            for (int f = 0; f < NF; f++) {
                const int d = DIMS_C[f];
                float s = 0.f;
                #pragma unroll
                for (int j0 = 0; j0 < d; j0 += 128) {
                    int j = j0 + lane * 4;
                    if (j < d) {
                        float4 a = *(const float4*)(p.feat[f] + (size_t)row * d + j);
                        float4 b = *(const float4*)(cs + OFFS_C[f] + j);
                        s += a.x * b.x + a.y * b.y + a.z * b.z + a.w * b.w;
                    }
                }
                #pragma unroll
                for (int o = 16; o; o >>= 1) s += __shfl_xor_sync(0xffffffffu, s, o);
                sc[f] = s;
            }
            float m = sc[0];
            #pragma unroll
            for (int f = 1; f < NF; f++) m = fmaxf(m, sc[f]);
            float sum = 0.f;
            #pragma unroll
            for (int f = 0; f < NF; f++) { sc[f] = expf(sc[f] - m); sum += sc[f]; }
            const float inv = 1.f / sum;
            if (lane == 0) {
                float4 w0 = make_float4(sc[0] * inv, sc[1] * inv, sc[2] * inv, sc[3] * inv);
                float4 w1 = make_float4(sc[4] * inv, sc[5] * inv, sc[6] * inv, sc[7] * inv);
                *(float4*)(ws_s + lrow * NF)     = w0;
                *(float4*)(ws_s + lrow * NF + 4) = w1;
                float* ao = out + (size_t)BATCHN * HID + (size_t)row * NF;
                *(float4*)(ao)     = w0;
                *(float4*)(ao + 4) = w1;
            }
        }
    }

    // ---- mainloop ----
    float acc[4][4][4];
    #pragma unroll
    for (int mf = 0; mf < 4; mf++)
        #pragma unroll
        for (int nf = 0; nf < 4; nf++)
            #pragma unroll
            for (int r = 0; r < 4; r++) acc[mf][nf][r] = 0.f;

    // per-lane ldmatrix base offsets (bytes)
    const uint32_t aoff = (uint32_t)((wm * 64 + (lane & 15)) * RSTRIDE + ((lane >> 4) * 8) * 2);
    const uint32_t boff = (uint32_t)((wn * 32 + ((lane >> 4) * 8) + (lane & 7)) * RSTRIDE +
                                     (((lane >> 3) & 1) * 8) * 2);
    const uint32_t sAh = sb + OFF_AH, sAl = sb + OFF_AL;
    const uint32_t sBh = sb + OFF_BH, sBl = sb + OFF_BL;

    for (int ch = 0; ch < NCH; ch++) {
        const int k0 = ch * KCH;
        __syncthreads();   // previous chunk's ldmatrix done (and phase-1 ws ready)

        // --- A convert: 128 rows x 64 k, hi/lo bf16, weight-scaled ---
        #pragma unroll
        for (int it = 0; it < 4; it++) {
            int g   = it * 256 + t;        // 0..1023
            int row = g >> 3;
            int kq  = g & 7;
            int kg  = k0 + kq * 8;
            int f   = ffind(kg);
            int j   = kg - gOFFS[f];
            const float* src = p.feat[f] + (size_t)(row0 + row) * gDIMS[f] + j;
            float4 v0 = *(const float4*)src;
            float4 v1 = *(const float4*)(src + 4);
            float w = ws_s[row * NF + f];
            float x[8] = {v0.x * w, v0.y * w, v0.z * w, v0.w * w,
                          v1.x * w, v1.y * w, v1.z * w, v1.w * w};
            uint32_t h[4], l[4];
            #pragma unroll
            for (int q = 0; q < 4; q++) {
                float a0 = x[2 * q], a1 = x[2 * q + 1];
                __nv_bfloat16 b0 = __float2bfloat16_rn(a0);
                __nv_bfloat16 b1 = __float2bfloat16_rn(a1);
                __nv_bfloat16 c0 = __float2bfloat16_rn(a0 - __bfloat162float(b0));
                __nv_bfloat16 c1 = __float2bfloat16_rn(a1 - __bfloat162float(b1));
                h[q] = (uint32_t)__bfloat16_as_ushort(b0) | ((uint32_t)__bfloat16_as_ushort(b1) << 16);
                l[q] = (uint32_t)__bfloat16_as_ushort(c0) | ((uint32_t)__bfloat16_as_ushort(c1) << 16);
            }
            uint32_t off = (uint32_t)(row * RSTRIDE + kq * 16);
            *(uint4*)(smem + OFF_AH + off) = make_uint4(h[0], h[1], h[2], h[3]);
            *(uint4*)(smem + OFF_AL + off) = make_uint4(l[0], l[1], l[2], l[3]);
        }
        // --- B tiles: copy from packed global (L2-resident) ---
        #pragma unroll
        for (int it = 0; it < 4; it++) {
            int g  = it * 256 + t;         // 0..1023
            int n  = g >> 3;
            int kq = g & 7;
            size_t goff = (size_t)n * KTOT + k0 + kq * 8;
            uint32_t off = (uint32_t)(n * RSTRIDE + kq * 16);
            *(uint4*)(smem + OFF_BH + off) = *(const uint4*)&g_Bh[goff];
            *(uint4*)(smem + OFF_BL + off) = *(const uint4*)&g_Bl[goff];
        }
        __syncthreads();

        // --- tensor-core phase: 4 k16 steps ---
        #pragma unroll
        for (int ks = 0; ks < 4; ks++) {
            const uint32_t koff = ks * 32;   // 16 bf16 = 32 bytes
            uint32_t a[4][4];
            #pragma unroll
            for (int mf = 0; mf < 4; mf++)
                ldsm_x4(a[mf], sAh + aoff + mf * (16 * RSTRIDE) + koff);

            uint32_t bh[4][2], bl[4][2];
            #pragma unroll
            for (int bq = 0; bq < 2; bq++) {
                uint32_t r[4];
                // B stored [n][k] k-contiguous -> NON-trans ldmatrix yields the
                // m16n8k16 row.col B fragment (lane: n = l>>2, two consecutive k)
                ldsm_x4(r, sBh + boff + bq * (16 * RSTRIDE) + koff);
                bh[bq * 2][0] = r[0]; bh[bq * 2][1] = r[1];
                bh[bq * 2 + 1][0] = r[2]; bh[bq * 2 + 1][1] = r[3];
                ldsm_x4(r, sBl + boff + bq * (16 * RSTRIDE) + koff);
                bl[bq * 2][0] = r[0]; bl[bq * 2][1] = r[1];
                bl[bq * 2 + 1][0] = r[2]; bl[bq * 2 + 1][1] = r[3];
            }
            #pragma unroll
            for (int mf = 0; mf < 4; mf++)
                #pragma unroll
                for (int nf = 0; nf < 4; nf++) mma_bf16(acc[mf][nf], a[mf], bh[nf]);
            #pragma unroll
            for (int mf = 0; mf < 4; mf++)
                #pragma unroll
                for (int nf = 0; nf < 4; nf++) mma_bf16(acc[mf][nf], a[mf], bl[nf]);
            // reload A lo over a[]
            #pragma unroll
            for (int mf = 0; mf < 4; mf++)
                ldsm_x4(a[mf], sAl + aoff + mf * (16 * RSTRIDE) + koff);
            #pragma unroll
            for (int mf = 0; mf < 4; mf++)
                #pragma unroll
                for (int nf = 0; nf < 4; nf++) mma_bf16(acc[mf][nf], a[mf], bh[nf]);
        }
    }

    // ---- epilogue: write combined ----
    #pragma unroll
    for (int mf = 0; mf < 4; mf++) {
        #pragma unroll
        for (int nf = 0; nf < 4; nf++) {
            int r0 = row0 + wm * 64 + mf * 16 + (lane >> 2);
            int c  = wn * 32 + nf * 8 + (lane & 3) * 2;
            *(float2*)(out + (size_t)r0 * HID + c) =
                make_float2(acc[mf][nf][0], acc[mf][nf][1]);
            *(float2*)(out + (size_t)(r0 + 8) * HID + c) =
                make_float2(acc[mf][nf][2], acc[mf][nf][3]);
        }
    }
}

// ---------------------------------------------------------------------------
extern "C" void kernel_launch(void* const* d_in, const int* in_sizes, int n_in,
                              void* d_out, int out_size) {
    static const int dims[NF] = {32, 64, 96, 128, 192, 256, 384, 512};
    Ptrs p;
    int wseen[NF] = {0};

    for (int i = 0; i < n_in; i++) {
        const float* ptr = (const float*)d_in[i];
        int s = in_sizes[i];
        if (s == HID) { p.q = ptr; continue; }
        bool matched = false;
        for (int f = 0; f < NF; f++)
            if (s == BATCHN * dims[f]) { p.feat[f] = ptr; matched = true; break; }
        if (matched) continue;
        for (int f = 0; f < NF; f++)
            if (s == HID * dims[f]) {
                if (!wseen[f]) { p.Wk[f] = ptr; wseen[f] = 1; }
                else           { p.Wv[f] = ptr; }
                break;
            }
    }

    cudaFuncSetAttribute(main_kernel, cudaFuncAttributeMaxDynamicSharedMemorySize, SMEM_TOT);

    prep_kernel<<<(HID * KTOT + 255) / 256, 256>>>(p);
    main_kernel<<<BATCHN / MBLK, NTHR, SMEM_TOT>>>(p, (float*)d_out);
}